// round 6
// baseline (speedup 1.0000x reference)
#include <cuda_runtime.h>
#include <math.h>
#include <stdint.h>

#define H 2048
#define HH (H*H)
#define TW 64                  // tile width (cols)
#define TH 16                  // tile height (rows)
#define IN_W 76                // input smem stride: cols c0-4 .. c0+71 (19 float4)
#define IN_H 20                // rows r0-2 .. r0+17
#define IN_HW (IN_H * IN_W)
#define YW 72                  // y smem stride: sc = gy - (c0-3)
#define YH 18                  // y rows: gyr = r0-1+ly, ly 0..17

__device__ __forceinline__ int dscalar(const int* p, int def) {
    return p ? p[0] : def;
}

__device__ __forceinline__ void cp_async16(uint32_t dst_smem, const void* src, int src_bytes) {
    asm volatile("cp.async.cg.shared.global [%0], [%1], 16, %2;\n"
                 :: "r"(dst_smem), "l"(src), "r"(src_bytes));
}
__device__ __forceinline__ void cp_async_commit_wait() {
    asm volatile("cp.async.commit_group;\n");
    asm volatile("cp.async.wait_group 0;\n" ::: "memory");
}

__global__ __launch_bounds__(256, 6)
void pgonet_main(const float* __restrict__ ref_speed,
                 const float* __restrict__ batch,
                 const float* __restrict__ x_tt,
                 const float* __restrict__ x_t,
                 const float* __restrict__ conv_v,
                 const float* __restrict__ conv_g,
                 const float* __restrict__ conv_b,
                 const float* __restrict__ ref_sol,
                 const int*   __restrict__ loc_x,
                 const int*   __restrict__ loc_y,
                 const int* p_bsize, const int* p_id,
                 const int* p_flag, const int* p_flag_num,
                 float* __restrict__ out, int P)
{
    __shared__ float s_in[3 * IN_HW];   // ch0=xtt ch1=xt ch2=speed
    __shared__ float s_y[YH * YW];
    __shared__ float s_W[28];
    __shared__ float s_b;

    const int tx = threadIdx.x & 15;      // 0..15 (float4 col group)
    const int ty = threadIdx.x >> 4;      // 0..15 (row)
    const int tid = threadIdx.x;
    const int r0 = blockIdx.y * TH;
    const int c0 = blockIdx.x * TW;

    const int bsize = dscalar(p_bsize, 10);
    const int ntb   = dscalar(p_flag, 1) - 1;
    const int step  = dscalar(p_flag_num, 1) - 1;
    const int i0    = ntb * bsize + step;
    const float* __restrict__ xtt_g = batch + (size_t)i0 * HH;
    const float* __restrict__ xt_g  = batch + (size_t)(i0 + 1) * HH;

    // ---- async-stage 3 x 20 x 76 floats: 3*20*19 = 1140 float4 groups ----
    uint32_t s_in_u32;
    {
        uint32_t a;
        asm("{ .reg .u64 t; cvta.to.shared.u64 t, %1; cvt.u32.u64 %0, t; }"
            : "=r"(a) : "l"(s_in));
        s_in_u32 = a;
    }
    #pragma unroll
    for (int it = 0; it < 5; it++) {
        int idx = tid + it * 256;
        if (idx < 3 * IN_H * 19) {
            int ch = idx / (IN_H * 19);
            int k  = idx - ch * (IN_H * 19);
            int lr = k / 19, lq = k - lr * 19;
            int gr = r0 - 2 + lr;
            int gc = c0 - 4 + 4 * lq;
            bool ok = (gr >= 0) && (gr < H) && (gc >= 0) && (gc + 3 < H);
            const float* p = (ch == 0) ? xtt_g : ((ch == 1) ? xt_g : ref_speed);
            const float* src = p + (ok ? ((size_t)gr * H + gc) : 0);
            uint32_t dst = s_in_u32 + 4u * (ch * IN_HW + lr * IN_W + 4 * lq);
            cp_async16(dst, src, ok ? 16 : 0);
        }
    }

    // ---- planes 0,1,3,4: pure copies (overlap with cp.async) ----
    {
        const int r = r0 + ty;
        size_t g = (size_t)r * H + c0 + 4 * tx;
        float4 a = *reinterpret_cast<const float4*>(x_tt + g);
        float4 b = *reinterpret_cast<const float4*>(x_t + g);
        *reinterpret_cast<float4*>(out + g)                  = a;
        *reinterpret_cast<float4*>(out + HH + g)             = b;
        *reinterpret_cast<float4*>(out + 3 * (size_t)HH + g) = a;
        *reinterpret_cast<float4*>(out + 4 * (size_t)HH + g) = b;
    }

    if (tid == 0) {
        float ss = 0.f;
        #pragma unroll
        for (int i = 0; i < 27; i++) { float v = conv_v[i]; ss += v * v; }
        float scale = conv_g[0] / sqrtf(ss);
        #pragma unroll
        for (int i = 0; i < 27; i++) s_W[i] = conv_v[i] * scale;
        s_b = conv_b[0];
    }

    cp_async_commit_wait();
    __syncthreads();

    const float* s_xtt = s_in;
    const float* s_xt  = s_in + IN_HW;
    const float* s_sp  = s_in + 2 * IN_HW;

    // ============ phase B (concurrent): conv on tid<81; xt4 on tid>=128 =====
    if (tid < 81) {
        // 8-wide x 2-row strips: p=row pair (0..8), q=col strip (0..8)
        const float bconv = s_b;
        int p = tid / 9, q = tid - p * 9;
        float acc0[8], acc1[8];
        #pragma unroll
        for (int k = 0; k < 8; k++) { acc0[k] = bconv; acc1[k] = bconv; }
        #pragma unroll
        for (int ch = 0; ch < 3; ch++) {
            #pragma unroll
            for (int ir = 0; ir < 4; ir++) {       // input row 2p+ir
                const float4* rp = reinterpret_cast<const float4*>(
                    s_in + ch * IN_HW + (2 * p + ir) * IN_W + 8 * q);
                float4 A = rp[0], B = rp[1], C = rp[2];
                float t[12] = {A.x, A.y, A.z, A.w, B.x, B.y, B.z, B.w,
                               C.x, C.y, C.z, C.w};
                if (ir < 3) {                       // out row 2p, kh=ir
                    float w0 = s_W[ch * 9 + ir * 3 + 0];
                    float w1 = s_W[ch * 9 + ir * 3 + 1];
                    float w2 = s_W[ch * 9 + ir * 3 + 2];
                    #pragma unroll
                    for (int k = 0; k < 8; k++) {
                        acc0[k] = fmaf(w0, t[k], acc0[k]);
                        acc0[k] = fmaf(w1, t[k + 1], acc0[k]);
                        acc0[k] = fmaf(w2, t[k + 2], acc0[k]);
                    }
                }
                if (ir >= 1) {                      // out row 2p+1, kh=ir-1
                    float w0 = s_W[ch * 9 + (ir - 1) * 3 + 0];
                    float w1 = s_W[ch * 9 + (ir - 1) * 3 + 1];
                    float w2 = s_W[ch * 9 + (ir - 1) * 3 + 2];
                    #pragma unroll
                    for (int k = 0; k < 8; k++) {
                        acc1[k] = fmaf(w0, t[k], acc1[k]);
                        acc1[k] = fmaf(w1, t[k + 1], acc1[k]);
                        acc1[k] = fmaf(w2, t[k + 2], acc1[k]);
                    }
                }
            }
        }
        float4* y0 = reinterpret_cast<float4*>(s_y + (2 * p) * YW + 8 * q);
        y0[0] = make_float4(acc0[0], acc0[1], acc0[2], acc0[3]);
        y0[1] = make_float4(acc0[4], acc0[5], acc0[6], acc0[7]);
        float4* y1 = reinterpret_cast<float4*>(s_y + (2 * p + 1) * YW + 8 * q);
        y1[0] = make_float4(acc1[0], acc1[1], acc1[2], acc1[3]);
        y1[1] = make_float4(acc1[4], acc1[5], acc1[6], acc1[7]);
    } else if (tid >= 128) {
        // xt4 (plane 6) for 2 rows per thread — overlaps conv
        int j = tid - 128;
        int tx2 = j & 15, ty2 = j >> 4;    // ty2 0..7
        #pragma unroll
        for (int h = 0; h < 2; h++) {
            int row = ty2 + h * 8;
            int rr = r0 + row;
            float4 xtC  = *reinterpret_cast<const float4*>(s_xt  + (row + 2) * IN_W + 4 * tx2 + 4);
            float4 xtU  = *reinterpret_cast<const float4*>(s_xt  + (row + 1) * IN_W + 4 * tx2 + 4);
            float4 xtD  = *reinterpret_cast<const float4*>(s_xt  + (row + 3) * IN_W + 4 * tx2 + 4);
            float  xtL  = s_xt[(row + 2) * IN_W + 4 * tx2 + 3];
            float  xtR  = s_xt[(row + 2) * IN_W + 4 * tx2 + 8];
            float4 xttC = *reinterpret_cast<const float4*>(s_xtt + (row + 2) * IN_W + 4 * tx2 + 4);
            float4 spC  = *reinterpret_cast<const float4*>(s_sp  + (row + 2) * IN_W + 4 * tx2 + 4);
            float xtc[4]  = {xtC.x, xtC.y, xtC.z, xtC.w};
            float xtu[4]  = {xtU.x, xtU.y, xtU.z, xtU.w};
            float xtd[4]  = {xtD.x, xtD.y, xtD.z, xtD.w};
            float xttc[4] = {xttC.x, xttC.y, xttC.z, xttC.w};
            float spc[4]  = {spC.x, spC.y, spC.z, spC.w};
            float xt4[4];
            #pragma unroll
            for (int jj = 0; jj < 4; jj++) {
                int c = c0 + 4 * tx2 + jj;
                float xl = (jj == 0) ? xtL : xtc[jj - 1];
                float xr = (jj == 3) ? xtR : xtc[jj + 1];
                float coef = spc[jj] * spc[jj] * 0.0025f;
                float base = 2.f * xtc[jj] - xttc[jj];
                bool interior = (rr > 0) & (rr < H - 1) & (c > 0) & (c < H - 1);
                float lap = xtu[jj] + xtd[jj] + xl + xr - 4.f * xtc[jj];
                xt4[jj] = interior ? (base + lap * coef) : 0.f;
            }
            size_t g = (size_t)rr * H + c0 + 4 * tx2;
            *reinterpret_cast<float4*>(out + 6 * (size_t)HH + g) =
                *reinterpret_cast<float4*>(xt4);
        }
    }
    __syncthreads();

    // ============ phase C: x7 / x7_pre (planes 2, 5), all 256 threads ======
    const int r = r0 + ty;
    const int cb = c0 + 4 * tx;

    float4 xtC  = *reinterpret_cast<const float4*>(s_xt  + (ty + 2) * IN_W + 4 * tx + 4);
    float  xtL  = s_xt[(ty + 2) * IN_W + 4 * tx + 3];
    float  xtR  = s_xt[(ty + 2) * IN_W + 4 * tx + 8];
    float4 xttC = *reinterpret_cast<const float4*>(s_xtt + (ty + 2) * IN_W + 4 * tx + 4);
    float4 spC  = *reinterpret_cast<const float4*>(s_sp  + (ty + 2) * IN_W + 4 * tx + 4);

    float yc8[8], yu8[8], yd8[8];
    {
        const float4* pc = reinterpret_cast<const float4*>(s_y + (ty + 1) * YW + 4 * tx);
        const float4* pu = reinterpret_cast<const float4*>(s_y + (ty    ) * YW + 4 * tx);
        const float4* pd = reinterpret_cast<const float4*>(s_y + (ty + 2) * YW + 4 * tx);
        float4 c0v = pc[0], c1v = pc[1];
        float4 u0v = pu[0], u1v = pu[1];
        float4 d0v = pd[0], d1v = pd[1];
        yc8[0]=c0v.x; yc8[1]=c0v.y; yc8[2]=c0v.z; yc8[3]=c0v.w;
        yc8[4]=c1v.x; yc8[5]=c1v.y; yc8[6]=c1v.z; yc8[7]=c1v.w;
        yu8[0]=u0v.x; yu8[1]=u0v.y; yu8[2]=u0v.z; yu8[3]=u0v.w;
        yu8[4]=u1v.x; yu8[5]=u1v.y; yu8[6]=u1v.z; yu8[7]=u1v.w;
        yd8[0]=d0v.x; yd8[1]=d0v.y; yd8[2]=d0v.z; yd8[3]=d0v.w;
        yd8[4]=d1v.x; yd8[5]=d1v.y; yd8[6]=d1v.z; yd8[7]=d1v.w;
    }

    float xtc[4]  = {xtC.x, xtC.y, xtC.z, xtC.w};
    float xttc[4] = {xttC.x, xttC.y, xttC.z, xttC.w};
    float spc[4]  = {spC.x, spC.y, spC.z, spC.w};

    float x7v[4], x7p[4];
    #pragma unroll
    for (int j = 0; j < 4; j++) {
        int c = cb + j;
        float xl = (j == 0) ? xtL : xtc[j - 1];
        float xr = (j == 3) ? xtR : xtc[j + 1];
        float ycn = yc8[j + 3];
        float yl  = yc8[j + 2];
        float yr2 = yc8[j + 4];

        float coef = spc[j] * spc[j] * 0.0025f;    // (DT/DX)^2
        float base = 2.f * xtc[j] - xttc[j];
        bool interior = (r > 0) & (r < H - 1) & (c > 0) & (c < H - 1);
        float lapy = yu8[j + 3] + yd8[j + 3] + yl + yr2 - 4.f * ycn;
        float p = interior ? (base + lapy * coef) : ycn;
        x7p[j] = p;

        float v = p;
        if (r == 0) v = 0.f;
        if (c == 0)     v = xtc[j] - 0.05f * spc[j] * (xtc[j] - xr);   // DT/DX
        if (r >= 1 && r <= H - 2 && c == H - r)
            v = s_xt[(ty + 1) * IN_W + 4 * tx + j + 3];                // xt[r-1,c-1]
        if (c == H - 1) v = xtc[j] - 0.05f * spc[j] * (xtc[j] - xl);
        if (r == H - 1) v = 0.f;
        x7v[j] = v;
    }

    size_t g = (size_t)r * H + cb;
    *reinterpret_cast<float4*>(out + 2 * (size_t)HH + g) = *reinterpret_cast<float4*>(x7v);
    *reinterpret_cast<float4*>(out + 5 * (size_t)HH + g) = *reinterpret_cast<float4*>(x7p);

    // ---- folded observation scatter (block owning pixel overrides plane 2) ----
    __syncthreads();
    if (tid < P) {
        int lx = loc_x[tid];
        if (lx != -1) {
            int lyv = loc_y[tid];
            if (lx >= r0 && lx < r0 + TH && lyv >= c0 && lyv < c0 + TW) {
                int id = dscalar(p_id, 1);
                size_t obs_off = (size_t)(id * bsize + step + 2) * HH;
                size_t gs = (size_t)lx * H + lyv;
                out[2 * (size_t)HH + gs] = ref_sol[obs_off + gs];
            }
        }
    }
}

extern "C" void kernel_launch(void* const* d_in, const int* in_sizes, int n_in,
                              void* d_out, int out_size)
{
    const float* ref_speed = (const float*)d_in[0];
    const float* batch     = (const float*)d_in[1];
    const float* x_tt      = (const float*)d_in[2];
    const float* x_t       = (const float*)d_in[3];
    const float* ref_sol   = (const float*)d_in[4];
    const float* conv_v    = (const float*)d_in[5];
    const float* conv_g    = (const float*)d_in[6];
    const float* conv_b    = (const float*)d_in[7];
    const int*   loc_x     = (const int*)d_in[8];
    const int*   loc_y     = (const int*)d_in[9];
    const int* p_bsize    = (n_in > 10) ? (const int*)d_in[10] : nullptr;
    const int* p_id       = (n_in > 11) ? (const int*)d_in[11] : nullptr;
    const int* p_flag     = (n_in > 12) ? (const int*)d_in[12] : nullptr;
    const int* p_flag_num = (n_in > 13) ? (const int*)d_in[13] : nullptr;

    float* out = (float*)d_out;
    int P = in_sizes[8];

    dim3 block(256);
    dim3 grid(H / TW, H / TH);
    pgonet_main<<<grid, block>>>(ref_speed, batch, x_tt, x_t,
                                 conv_v, conv_g, conv_b,
                                 ref_sol, loc_x, loc_y,
                                 p_bsize, p_id, p_flag, p_flag_num,
                                 out, P);
}